// round 12
// baseline (speedup 1.0000x reference)
#include <cuda_runtime.h>
#include <cuda_fp16.h>
#include <cstdint>

// ---------------------------------------------------------------------------
//   c3   : [16, 512, 64, 64] f32
//   c4   : [16,1024, 32, 32] f32
//   boxes: [16, 10, 4] f32
//   w    : [512, 1536] f32
//   out  : boxes (640 f32) ++ obj_blob [16,10,512,5,5]
// ---------------------------------------------------------------------------
#define OC   512
#define HW   4096
#define KD   1536
#define NKT  96                    // K / 16

// Scratch (device globals — allocation-free)
__device__ __align__(128) uint32_t g_wpack[OC * KD / 2];          // 1.5 MB
__device__ __align__(128) __half   g_attrh[16L * OC * HW + 256];  // 64 MB fp16

// ---------------------------------------------------------------------------
// PTX helpers (baseline ISA only)
// ---------------------------------------------------------------------------
__device__ __forceinline__ uint32_t smem_u32(const void* p) {
    uint32_t a;
    asm("{ .reg .u64 t; cvta.to.shared.u64 t, %1; cvt.u32.u64 %0, t; }" : "=r"(a) : "l"(p));
    return a;
}
__device__ __forceinline__ void cp16(uint32_t dst, const void* src) {
    asm volatile("cp.async.cg.shared.global [%0], [%1], 16;" :: "r"(dst), "l"(src));
}
#define CP_COMMIT() asm volatile("cp.async.commit_group;" ::: "memory")
#define CP_WAIT2()  asm volatile("cp.async.wait_group 2;" ::: "memory")

__device__ __forceinline__ uint32_t pack_h2(float lo, float hi) {
    __half2 h = __floats2half2_rn(lo, hi);
    return *(uint32_t*)&h;
}
__device__ __forceinline__ void mma_f16(float* c, const uint32_t* a,
                                        uint32_t b0, uint32_t b1) {
    asm volatile(
        "mma.sync.aligned.m16n8k16.row.col.f32.f16.f16.f32 "
        "{%0,%1,%2,%3}, {%4,%5,%6,%7}, {%8,%9}, {%0,%1,%2,%3};"
        : "+f"(c[0]), "+f"(c[1]), "+f"(c[2]), "+f"(c[3])
        : "r"(a[0]), "r"(a[1]), "r"(a[2]), "r"(a[3]), "r"(b0), "r"(b1));
}

// ---------------------------------------------------------------------------
// Kernel 0: pack W -> fp16 A-fragment order (m16n8k16 layout)
// ---------------------------------------------------------------------------
__global__ void wpack_kernel(const float* __restrict__ w) {
    const int i = blockIdx.x * 256 + threadIdx.x;
    if (i >= 32 * NKT * 32) return;
    const int t = i >> 5, lane = i & 31;
    const int mt = t / NKT, kt = t % NKT;
    const int r = lane >> 2, c = lane & 3;
    const float* w0 = w + (long)(mt * 16 + r) * KD + kt * 16 + 2 * c;
    const float* w8 = w0 + 8 * KD;
    uint4 v;
    v.x = pack_h2(w0[0], w0[1]);
    v.y = pack_h2(w8[0], w8[1]);
    v.z = pack_h2(w0[8], w0[9]);
    v.w = pack_h2(w8[8], w8[9]);
    ((uint4*)g_wpack)[i] = v;
}

// ---------------------------------------------------------------------------
// Kernel 1 (was 2): fp16 mma.sync GEMM with IN-KERNEL B production.
//   B tile (128 hw x 32 ch) built per stage directly from c3 / bilinear(c4):
//   no intermediate g_bpack tensor. CTA 128x128, BK=32, 4-stage pipeline,
//   A via cp.async, B via LDG->pack->STS. B tile stride padded to 264B so
//   producer STS is >=2-way-conflict max and consumer LDS.64 stays clean.
// ---------------------------------------------------------------------------
#define STAGES    4
#define A_BYTES   8192
#define B_OFF     A_BYTES
#define B_TILE_STRIDE 264                    // 256 + 8 pad
#define STG_BYTES (A_BYTES + 32 * B_TILE_STRIDE)   // 16640
#define BN_OFF    (STAGES * STG_BYTES)              // 66560
#define GEMM_SMEM (BN_OFF + 1024)

__global__ __launch_bounds__(256, 2)
void gemm_kernel(const float* __restrict__ c3,   const float* __restrict__ c4,
                 const float* __restrict__ bconv, const float* __restrict__ gamma,
                 const float* __restrict__ beta,  const float* __restrict__ mean,
                 const float* __restrict__ var) {
    extern __shared__ char smem[];
    const uint32_t sb = smem_u32(smem);
    const int tid  = threadIdx.x;
    const int wid  = tid >> 5, lane = tid & 31;
    const int wm   = wid >> 2;
    const int wn   = wid & 3;
    const int m0   = blockIdx.x * 128;
    const int ny   = blockIdx.y;
    const int bI   = ny >> 5;
    const int hw0  = (ny & 31) * 128;
    const int h0   = (ny & 31) * 2;           // two full rows h0, h0+1

    float* s_inv  = (float*)(smem + BN_OFF);
    float* s_bias = s_inv + 128;
    if (tid < 128) {
        const int o = m0 + tid;
        const float iv = gamma[o] * rsqrtf(var[o] + 1e-5f);
        s_inv[tid]  = iv;
        s_bias[tid] = (bconv[o] - mean[o]) * iv + beta[o];
    }

    // ---- A loader (cp.async, unchanged fragment layout) ----
    const uint4* Wp = (const uint4*)g_wpack;
    const int mtb = blockIdx.x * 8;
    long  aG[2];
    uint32_t aS[2];
#pragma unroll
    for (int j = 0; j < 2; ++j) {
        const int u = tid + j * 256;
        const int mt_l = u >> 6, kt_l = (u >> 5) & 1, ln = u & 31;
        aG[j] = ((long)(mtb + mt_l) * NKT + kt_l) * 32 + ln;
        aS[j] = (uint32_t)u * 16;
    }

    // ---- B producer thread constants ----
    const int cI  = tid >> 4;                 // 0..15: k-pair within 32-ch stage
    const int nt  = tid & 15;                 // 0..15: hw octet
    const int q   = nt & 7;                   // w-octet
    const int hR  = h0 + (nt >> 3);           // absolute row for this thread
    const int cc7 = cI & 7;
    const int jj  = 2 * (cc7 & 3) + (cc7 >> 2);
    const int ktl = cI >> 3;
    const uint32_t bStsOff = (uint32_t)(B_OFF + (nt * 2 + ktl) * B_TILE_STRIDE + jj * 4);

    // y-interp constants (row fixed per thread)
    const float syf = hR * 0.5f - 0.25f;
    const float y0f = floorf(syf);
    const float fy  = syf - y0f;
    const int iy0 = max(0, min(31, (int)y0f));
    const int iy1 = max(0, min(31, (int)y0f + 1));
    // x source columns (6 fixed per thread)
    int colx[6];
#pragma unroll
    for (int s = 0; s < 6; ++s) colx[s] = max(0, min(31, 4 * q - 1 + s));

    auto produce_B = [&](int t) {
        const int k0 = t * 32;
        uint32_t u[8];
        if (k0 < 512) {
            // c3: channels (k0+2c, k0+2c+1), 8 consecutive w — coalesced f32x4
            const long base = (((long)(bI * 512 + k0 + 2 * cI)) << 12) + hR * 64 + q * 8;
            const float4 f0a = *(const float4*)(c3 + base);
            const float4 f0b = *(const float4*)(c3 + base + 4);
            const float4 f1a = *(const float4*)(c3 + base + HW);
            const float4 f1b = *(const float4*)(c3 + base + HW + 4);
            u[0] = pack_h2(f0a.x, f1a.x); u[1] = pack_h2(f0a.y, f1a.y);
            u[2] = pack_h2(f0a.z, f1a.z); u[3] = pack_h2(f0a.w, f1a.w);
            u[4] = pack_h2(f0b.x, f1b.x); u[5] = pack_h2(f0b.y, f1b.y);
            u[6] = pack_h2(f0b.z, f1b.z); u[7] = pack_h2(f0b.w, f1b.w);
        } else {
            // c4: inline bilinear 2x upsample for channels (cc, cc+1)
            const int cc = k0 - 512 + 2 * cI;
            const float* baseA = c4 + ((long)(bI * 1024 + cc)) * 1024;
            const float* rA0 = baseA + iy0 * 32;
            const float* rA1 = baseA + iy1 * 32;
            const float* rB0 = rA0 + 1024;
            const float* rB1 = rA1 + 1024;
            float cA0[6], cA1[6], cB0[6], cB1[6];
#pragma unroll
            for (int s = 0; s < 6; ++s) {
                const int cx = colx[s];
                cA0[s] = __ldg(rA0 + cx);
                cA1[s] = __ldg(rA1 + cx);
                cB0[s] = __ldg(rB0 + cx);
                cB1[s] = __ldg(rB1 + cx);
            }
#pragma unroll
            for (int wi = 0; wi < 8; ++wi) {
                const int r0 = (wi + 1) >> 1;       // compile-time per unrolled wi
                const int r1 = r0 + 1;
                const float fx = (wi & 1) ? 0.25f : 0.75f;
                const float wa = (1.f - fx) * (1.f - fy), wb = fx * (1.f - fy);
                const float wc = (1.f - fx) * fy,          wd = fx * fy;
                const float vA = cA0[r0] * wa + cA0[r1] * wb +
                                 cA1[r0] * wc + cA1[r1] * wd;
                const float vB = cB0[r0] * wa + cB0[r1] * wb +
                                 cB1[r0] * wc + cB1[r1] * wd;
                u[wi] = pack_h2(vA, vB);
            }
        }
        char* stg = smem + (t & (STAGES - 1)) * STG_BYTES;
#pragma unroll
        for (int i2 = 0; i2 < 8; ++i2)
            *(uint32_t*)(stg + bStsOff + i2 * 32) = u[i2];
    };

    float acc[4][4][4];
#pragma unroll
    for (int i = 0; i < 4; i++)
#pragma unroll
        for (int j = 0; j < 4; j++)
#pragma unroll
            for (int k = 0; k < 4; k++) acc[i][j][k] = 0.f;

    // prologue: 3 stages in flight
#pragma unroll
    for (int s = 0; s < STAGES - 1; ++s) {
        const uint32_t stg = sb + s * STG_BYTES;
        cp16(stg + aS[0], Wp + aG[0] + (long)s * 64);
        cp16(stg + aS[1], Wp + aG[1] + (long)s * 64);
        CP_COMMIT();
        produce_B(s);
    }

    for (int t = 0; t < 48; ++t) {
        CP_WAIT2();
        __syncthreads();
        if (t + STAGES - 1 < 48) {
            const int tn = t + STAGES - 1;
            const uint32_t stg = sb + (tn & (STAGES - 1)) * STG_BYTES;
            cp16(stg + aS[0], Wp + aG[0] + (long)tn * 64);
            cp16(stg + aS[1], Wp + aG[1] + (long)tn * 64);
            produce_B(tn);
        }
        CP_COMMIT();

        const uint32_t stg = sb + (t & (STAGES - 1)) * STG_BYTES;
#pragma unroll
        for (int kg = 0; kg < 2; ++kg) {
            uint32_t bf[4][2];
#pragma unroll
            for (int nf = 0; nf < 4; ++nf) {
                const uint32_t ba = stg + B_OFF +
                    (uint32_t)(((wn * 4 + nf) * 2 + kg) * B_TILE_STRIDE + lane * 8);
                asm volatile("ld.shared.v2.b32 {%0,%1}, [%2];"
                             : "=r"(bf[nf][0]), "=r"(bf[nf][1]) : "r"(ba));
            }
#pragma unroll
            for (int mf = 0; mf < 4; ++mf) {
                uint32_t af[4];
                const uint32_t aa = stg +
                    (uint32_t)((((wm * 4 + mf) * 2 + kg) * 32 + lane) * 16);
                asm volatile("ld.shared.v4.b32 {%0,%1,%2,%3}, [%4];"
                             : "=r"(af[0]), "=r"(af[1]), "=r"(af[2]), "=r"(af[3])
                             : "r"(aa));
#pragma unroll
                for (int nf = 0; nf < 4; ++nf)
                    mma_f16(acc[mf][nf], af, bf[nf][0], bf[nf][1]);
            }
        }
    }

    // epilogue: BN + relu -> fp16 attr (half2 stores)
    const int g = lane >> 2, tq = lane & 3;
    __half* attrh = g_attrh + ((long)bI * OC + m0) * HW + hw0;
#pragma unroll
    for (int mf = 0; mf < 4; ++mf) {
        const int ml0 = wm * 64 + mf * 16 + g;
        const int ml1 = ml0 + 8;
        const float i0 = s_inv[ml0], z0 = s_bias[ml0];
        const float i1 = s_inv[ml1], z1 = s_bias[ml1];
#pragma unroll
        for (int nf = 0; nf < 4; ++nf) {
            const int n = wn * 32 + nf * 8 + 2 * tq;
            *(__half2*)(attrh + (long)ml0 * HW + n) =
                __floats2half2_rn(fmaxf(acc[mf][nf][0] * i0 + z0, 0.f),
                                  fmaxf(acc[mf][nf][1] * i0 + z0, 0.f));
            *(__half2*)(attrh + (long)ml1 * HW + n) =
                __floats2half2_rn(fmaxf(acc[mf][nf][2] * i1 + z1, 0.f),
                                  fmaxf(acc[mf][nf][3] * i1 + z1, 0.f));
        }
    }
}

// ---------------------------------------------------------------------------
// Kernel 2: ROI adaptive-avg-pool 5x5 over fp16 attr.  grid (160, 64).
// ---------------------------------------------------------------------------
__global__ __launch_bounds__(256) void pool_kernel(const float* __restrict__ boxes,
                                                   float* __restrict__ obj) {
    const int br = blockIdx.x;
    const int b  = br / 10;
    const float* bx = boxes + br * 4;

    int x1 = min(63, max(0, (int)floorf(bx[0] * 0.125f)));
    int y1 = min(63, max(0, (int)floorf(bx[1] * 0.125f)));
    int x2 = min(63, max(0, (int)ceilf (bx[2] * 0.125f)));
    int y2 = min(63, max(0, (int)ceilf (bx[3] * 0.125f)));
    if (x2 <= x1) x2 = min(x1 + 1, 64);
    if (y2 <= y1) y2 = min(y1 + 1, 64);
    const int Lx = x2 - x1, Ly = y2 - y1;

    int xs[5], xe[5], ys[5], ye[5];
    float invx[5], invy[5];
#pragma unroll
    for (int k = 0; k < 5; k++) {
        xs[k] = x1 + (k * Lx) / 5;
        xe[k] = x1 + ((k + 1) * Lx + 4) / 5;
        ys[k] = y1 + (k * Ly) / 5;
        ye[k] = y1 + ((k + 1) * Ly + 4) / 5;
        invx[k] = 1.f / (float)(xe[k] - xs[k]);
        invy[k] = 1.f / (float)(ye[k] - ys[k]);
    }

    const int warp = threadIdx.x >> 5, lane = threadIdx.x & 31;
    const int c = blockIdx.y * 8 + warp;
    const int cb = x1 & ~1;
    const int col0 = cb + 2 * lane, col1 = col0 + 1;
    const bool inx = (col1 >= x1) && (col0 < x2);
    const __half2* ch2 = (const __half2*)(g_attrh + ((long)b * OC + c) * HW) +
                         (cb >> 1) + lane;

    float2 cs[5];
#pragma unroll
    for (int p = 0; p < 5; p++) cs[p] = make_float2(0.f, 0.f);

    if (inx) {
#pragma unroll 4
        for (int h = y1; h < y2; h++) {
            const float2 v = __half22float2(ch2[h * 32]);
#pragma unroll
            for (int p = 0; p < 5; p++)
                if (h >= ys[p] && h < ye[p]) {
                    cs[p].x += v.x * invy[p];
                    cs[p].y += v.y * invy[p];
                }
        }
    }

    float bins[25];
#pragma unroll
    for (int q = 0; q < 5; q++) {
        const float w0 = (col0 >= xs[q] && col0 < xe[q]) ? invx[q] : 0.f;
        const float w1 = (col1 >= xs[q] && col1 < xe[q]) ? invx[q] : 0.f;
#pragma unroll
        for (int p = 0; p < 5; p++)
            bins[p * 5 + q] = cs[p].x * w0 + cs[p].y * w1;
    }
#pragma unroll
    for (int t = 0; t < 25; t++) {
        float v = bins[t];
        v += __shfl_xor_sync(0xffffffffu, v, 16);
        v += __shfl_xor_sync(0xffffffffu, v, 8);
        v += __shfl_xor_sync(0xffffffffu, v, 4);
        v += __shfl_xor_sync(0xffffffffu, v, 2);
        v += __shfl_xor_sync(0xffffffffu, v, 1);
        bins[t] = v;
    }
    if (lane < 25) {
        float vout = 0.f;
#pragma unroll
        for (int t = 0; t < 25; t++)
            if (lane == t) vout = bins[t];
        obj[((long)br * OC + c) * 25 + lane] = vout;
    }
}

__global__ void copy_boxes_kernel(const float* __restrict__ boxes,
                                  float* __restrict__ out) {
    int i = blockIdx.x * blockDim.x + threadIdx.x;
    if (i < 640) out[i] = boxes[i];
}

// ---------------------------------------------------------------------------
extern "C" void kernel_launch(void* const* d_in, const int* in_sizes, int n_in,
                              void* d_out, int out_size) {
    const float* c3    = (const float*)d_in[0];
    const float* c4    = (const float*)d_in[1];
    const float* boxes = (const float*)d_in[2];
    const float* w     = (const float*)d_in[3];
    const float* bconv = (const float*)d_in[4];
    const float* gamma = (const float*)d_in[5];
    const float* beta  = (const float*)d_in[6];
    const float* mean  = (const float*)d_in[7];
    const float* var   = (const float*)d_in[8];

    float* out = (float*)d_out;
    float* obj = out;
    if (out_size >= 640 + 16 * 10 * 512 * 25) {
        copy_boxes_kernel<<<3, 256>>>(boxes, out);
        obj = out + 640;
    }

    cudaFuncSetAttribute(gemm_kernel, cudaFuncAttributeMaxDynamicSharedMemorySize,
                         GEMM_SMEM);

    wpack_kernel<<<(32 * NKT * 32 + 255) / 256, 256>>>(w);
    gemm_kernel<<<dim3(4, 512), 256, GEMM_SMEM>>>(c3, c4, bconv, gamma, beta,
                                                  mean, var);
    pool_kernel<<<dim3(160, 64), 256>>>(boxes, obj);
}

// round 14
// speedup vs baseline: 1.4994x; 1.4994x over previous
#include <cuda_runtime.h>
#include <cuda_fp16.h>
#include <cstdint>

// ---------------------------------------------------------------------------
//   c3   : [16, 512, 64, 64] f32
//   c4   : [16,1024, 32, 32] f32
//   boxes: [16, 10, 4] f32
//   w    : [512, 1536] f32
//   out  : boxes (640 f32) ++ obj_blob [16,10,512,5,5]
// ---------------------------------------------------------------------------
#define OC   512
#define HW   4096
#define KD   1536
#define NKT  96                    // K / 16

// Scratch (device globals — allocation-free)
__device__ __align__(128) uint32_t g_wpack[OC * KD / 2];          // 1.5 MB
__device__ __align__(128) uint32_t g_bpack[16L * HW * KD / 2];    // 192 MB
__device__ __align__(128) __half   g_attrh[16L * OC * HW + 256];  // 64 MB fp16

// ---------------------------------------------------------------------------
// PTX helpers (baseline ISA only)
// ---------------------------------------------------------------------------
__device__ __forceinline__ uint32_t smem_u32(const void* p) {
    uint32_t a;
    asm("{ .reg .u64 t; cvta.to.shared.u64 t, %1; cvt.u32.u64 %0, t; }" : "=r"(a) : "l"(p));
    return a;
}
__device__ __forceinline__ void cp16(uint32_t dst, const void* src) {
    asm volatile("cp.async.cg.shared.global [%0], [%1], 16;" :: "r"(dst), "l"(src));
}
#define CP_COMMIT() asm volatile("cp.async.commit_group;" ::: "memory")
#define CP_WAIT2()  asm volatile("cp.async.wait_group 2;" ::: "memory")

__device__ __forceinline__ uint32_t pack_h2(float lo, float hi) {
    __half2 h = __floats2half2_rn(lo, hi);
    return *(uint32_t*)&h;
}
__device__ __forceinline__ void mma_f16(float* c, const uint32_t* a,
                                        uint32_t b0, uint32_t b1) {
    asm volatile(
        "mma.sync.aligned.m16n8k16.row.col.f32.f16.f16.f32 "
        "{%0,%1,%2,%3}, {%4,%5,%6,%7}, {%8,%9}, {%0,%1,%2,%3};"
        : "+f"(c[0]), "+f"(c[1]), "+f"(c[2]), "+f"(c[3])
        : "r"(a[0]), "r"(a[1]), "r"(a[2]), "r"(a[3]), "r"(b0), "r"(b1));
}

// ---------------------------------------------------------------------------
// Kernel 0: pack W -> fp16 A-fragment order (m16n8k16 layout)
// ---------------------------------------------------------------------------
__global__ void wpack_kernel(const float* __restrict__ w) {
    const int i = blockIdx.x * 256 + threadIdx.x;
    if (i >= 32 * NKT * 32) return;
    const int t = i >> 5, lane = i & 31;
    const int mt = t / NKT, kt = t % NKT;
    const int r = lane >> 2, c = lane & 3;
    const float* w0 = w + (long)(mt * 16 + r) * KD + kt * 16 + 2 * c;
    const float* w8 = w0 + 8 * KD;
    uint4 v;
    v.x = pack_h2(w0[0], w0[1]);
    v.y = pack_h2(w8[0], w8[1]);
    v.z = pack_h2(w0[8], w0[9]);
    v.w = pack_h2(w8[8], w8[9]);
    ((uint4*)g_wpack)[i] = v;
}

// ---------------------------------------------------------------------------
// Kernel 1: fused = concat(c3, bilinear2x(c4)) -> fp16 B-fragment-packed
//   grid (16 b, 24 ctile, 16 hquad), block 256.  Block: 64 ch x 64 w x 4 h.
// ---------------------------------------------------------------------------
__global__ __launch_bounds__(256) void fuse_kernel(const float* __restrict__ c3,
                                                   const float* __restrict__ c4) {
    __shared__ uint32_t s[4][64][33];       // [h][w][c2]: channels 2c2, 2c2+1
    const int b   = blockIdx.x;
    const int ct  = blockIdx.y;
    const int h0  = blockIdx.z * 4;
    const int tid = threadIdx.x;
    const int c0  = ct * 64;

    if (c0 < 512) {
#pragma unroll
        for (int hh = 0; hh < 4; ++hh) {
#pragma unroll
            for (int it = 0; it < 2; ++it) {
                const int i  = tid + it * 256;
                const int w4 = i & 15, c2 = i >> 4;
                const long base = (((long)(b * 512 + c0 + 2 * c2)) << 12) +
                                  (h0 + hh) * 64 + w4 * 4;
                const float4 f0 = *(const float4*)(c3 + base);
                const float4 f1 = *(const float4*)(c3 + base + HW);
                s[hh][w4 * 4 + 0][c2] = pack_h2(f0.x, f1.x);
                s[hh][w4 * 4 + 1][c2] = pack_h2(f0.y, f1.y);
                s[hh][w4 * 4 + 2][c2] = pack_h2(f0.z, f1.z);
                s[hh][w4 * 4 + 3][c2] = pack_h2(f0.w, f1.w);
            }
        }
    } else {
        const int cc0 = c0 - 512;
#pragma unroll
        for (int hh = 0; hh < 4; ++hh) {
            const int h = h0 + hh;
            const float syf = h * 0.5f - 0.25f;
            const float y0f = floorf(syf);
            const float fy  = syf - y0f;
            const int  iy0 = max(0, min(31, (int)y0f));
            const int  iy1 = max(0, min(31, (int)y0f + 1));
#pragma unroll
            for (int it = 0; it < 2; ++it) {
                const int i  = tid + it * 256;
                const int w4 = i & 15, c2 = i >> 4;
                const float* srcA = c4 + ((long)(b * 1024 + cc0 + 2 * c2)) * 1024;
                const float* srcB = srcA + 1024;
                const float* a0 = srcA + iy0 * 32;
                const float* a1 = srcA + iy1 * 32;
                const float* b0p = srcB + iy0 * 32;
                const float* b1p = srcB + iy1 * 32;
#pragma unroll
                for (int j = 0; j < 4; ++j) {
                    const int w = w4 * 4 + j;
                    const float sxf = w * 0.5f - 0.25f;
                    const float x0f = floorf(sxf);
                    const float fx  = sxf - x0f;
                    const int ix0 = max(0, min(31, (int)x0f));
                    const int ix1 = max(0, min(31, (int)x0f + 1));
                    const float wa = (1.f - fx) * (1.f - fy), wb = fx * (1.f - fy);
                    const float wc = (1.f - fx) * fy,          wd = fx * fy;
                    const float vA = a0[ix0] * wa + a0[ix1] * wb +
                                     a1[ix0] * wc + a1[ix1] * wd;
                    const float vB = b0p[ix0] * wa + b0p[ix1] * wb +
                                     b1p[ix0] * wc + b1p[ix1] * wd;
                    s[hh][w][c2] = pack_h2(vA, vB);
                }
            }
        }
    }
    __syncthreads();

    for (int i = tid; i < 1024; i += 256) {
        const int w   = i & 63;
        const int ktl = (i >> 6) & 3;
        const int hh  = i >> 8;
        const uint32_t* row = &s[hh][w][0] + ktl * 8;
        uint4 lo = make_uint4(row[0], row[4], row[1], row[5]);
        uint4 hi = make_uint4(row[2], row[6], row[3], row[7]);
        const int  h    = h0 + hh;
        const long nt   = (long)b * 512 + ((h * 64 + w) >> 3);
        const long base = (nt * NKT + ct * 4 + ktl) * 64 + (w & 7) * 8;
        *(uint4*)(g_bpack + base)     = lo;
        *(uint4*)(g_bpack + base + 4) = hi;
    }
}

// ---------------------------------------------------------------------------
// Kernel 2: fp16 mma.sync GEMM, 4-stage single-sync cp.async pipeline
//   CTA 128x128, BK=32, 8 warps (2m x 4n), warp tile 64x32.  grid (4, 512).
// ---------------------------------------------------------------------------
#define STAGES    4
#define STG_BYTES 16384
#define B_OFF 8192
#define BN_OFF (STAGES * STG_BYTES)
#define GEMM_SMEM (BN_OFF + 1024)

__global__ __launch_bounds__(256, 2)
void gemm_kernel(const float* __restrict__ bconv, const float* __restrict__ gamma,
                 const float* __restrict__ beta,  const float* __restrict__ mean,
                 const float* __restrict__ var) {
    extern __shared__ char smem[];
    const uint32_t sb = smem_u32(smem);
    const int tid  = threadIdx.x;
    const int wid  = tid >> 5, lane = tid & 31;
    const int wm   = wid >> 2;
    const int wn   = wid & 3;
    const int m0   = blockIdx.x * 128;
    const int ny   = blockIdx.y;
    const int bI   = ny >> 5;
    const int hw0  = (ny & 31) * 128;

    float* s_inv  = (float*)(smem + BN_OFF);
    float* s_bias = s_inv + 128;
    if (tid < 128) {
        const int o = m0 + tid;
        const float iv = gamma[o] * rsqrtf(var[o] + 1e-5f);
        s_inv[tid]  = iv;
        s_bias[tid] = (bconv[o] - mean[o]) * iv + beta[o];
    }

    const uint4* Wp = (const uint4*)g_wpack;
    const uint4* Bp = (const uint4*)g_bpack;
    const int  mtb = blockIdx.x * 8;
    const long ntb = (long)bI * 512 + (ny & 31) * 16;

    long  aG[2], bG[2];
    uint32_t aS[2], bS[2];
#pragma unroll
    for (int j = 0; j < 2; ++j) {
        const int u = tid + j * 256;
        {
            const int mt_l = u >> 6, kt_l = (u >> 5) & 1, ln = u & 31;
            aG[j] = ((long)(mtb + mt_l) * NKT + kt_l) * 32 + ln;
            aS[j] = (uint32_t)u * 16;
        }
        {
            const int nt_l = u >> 5, kt_l = (u >> 4) & 1, p = u & 15;
            bG[j] = ((ntb + nt_l) * NKT + kt_l) * 16 + p;
            bS[j] = (uint32_t)(B_OFF + u * 16);
        }
    }

    auto load_stage = [&](int buf, int t) {
        const uint32_t stg = sb + buf * STG_BYTES;
#pragma unroll
        for (int j = 0; j < 2; ++j) {
            cp16(stg + aS[j], Wp + aG[j] + (long)t * 64);
            cp16(stg + bS[j], Bp + bG[j] + (long)t * 32);
        }
    };

    float acc[4][4][4];
#pragma unroll
    for (int i = 0; i < 4; i++)
#pragma unroll
        for (int j = 0; j < 4; j++)
#pragma unroll
            for (int k = 0; k < 4; k++) acc[i][j][k] = 0.f;

#pragma unroll
    for (int s = 0; s < STAGES - 1; ++s) { load_stage(s, s); CP_COMMIT(); }

    for (int t = 0; t < 48; ++t) {
        CP_WAIT2();
        __syncthreads();
        if (t + STAGES - 1 < 48) load_stage((t + STAGES - 1) & (STAGES - 1), t + STAGES - 1);
        CP_COMMIT();

        const uint32_t stg = sb + (t & (STAGES - 1)) * STG_BYTES;
#pragma unroll
        for (int kg = 0; kg < 2; ++kg) {
            uint32_t bf[4][2];
#pragma unroll
            for (int nf = 0; nf < 4; ++nf) {
                const uint32_t ba = stg + B_OFF +
                    (uint32_t)(((wn * 4 + nf) * 2 + kg) * 256 + lane * 8);
                asm volatile("ld.shared.v2.b32 {%0,%1}, [%2];"
                             : "=r"(bf[nf][0]), "=r"(bf[nf][1]) : "r"(ba));
            }
#pragma unroll
            for (int mf = 0; mf < 4; ++mf) {
                uint32_t af[4];
                const uint32_t aa = stg +
                    (uint32_t)((((wm * 4 + mf) * 2 + kg) * 32 + lane) * 16);
                asm volatile("ld.shared.v4.b32 {%0,%1,%2,%3}, [%4];"
                             : "=r"(af[0]), "=r"(af[1]), "=r"(af[2]), "=r"(af[3])
                             : "r"(aa));
#pragma unroll
                for (int nf = 0; nf < 4; ++nf)
                    mma_f16(acc[mf][nf], af, bf[nf][0], bf[nf][1]);
            }
        }
    }

    const int g = lane >> 2, tq = lane & 3;
    __half* attrh = g_attrh + ((long)bI * OC + m0) * HW + hw0;
#pragma unroll
    for (int mf = 0; mf < 4; ++mf) {
        const int ml0 = wm * 64 + mf * 16 + g;
        const int ml1 = ml0 + 8;
        const float i0 = s_inv[ml0], z0 = s_bias[ml0];
        const float i1 = s_inv[ml1], z1 = s_bias[ml1];
#pragma unroll
        for (int nf = 0; nf < 4; ++nf) {
            const int n = wn * 32 + nf * 8 + 2 * tq;
            *(__half2*)(attrh + (long)ml0 * HW + n) =
                __floats2half2_rn(fmaxf(acc[mf][nf][0] * i0 + z0, 0.f),
                                  fmaxf(acc[mf][nf][1] * i0 + z0, 0.f));
            *(__half2*)(attrh + (long)ml1 * HW + n) =
                __floats2half2_rn(fmaxf(acc[mf][nf][2] * i1 + z1, 0.f),
                                  fmaxf(acc[mf][nf][3] * i1 + z1, 0.f));
        }
    }
}

// ---------------------------------------------------------------------------
// Kernel 3: ROI adaptive-avg-pool 5x5 over fp16 attr.  grid (160, 64).
//   Bin-outer row loops: no per-row range predicates (overlap rows re-read
//   from L1).  Lanes outside the box skip all loads.
// ---------------------------------------------------------------------------
__global__ __launch_bounds__(256) void pool_kernel(const float* __restrict__ boxes,
                                                   float* __restrict__ obj) {
    const int br = blockIdx.x;
    const int b  = br / 10;
    const float* bx = boxes + br * 4;

    int x1 = min(63, max(0, (int)floorf(bx[0] * 0.125f)));
    int y1 = min(63, max(0, (int)floorf(bx[1] * 0.125f)));
    int x2 = min(63, max(0, (int)ceilf (bx[2] * 0.125f)));
    int y2 = min(63, max(0, (int)ceilf (bx[3] * 0.125f)));
    if (x2 <= x1) x2 = min(x1 + 1, 64);
    if (y2 <= y1) y2 = min(y1 + 1, 64);
    const int Lx = x2 - x1, Ly = y2 - y1;

    int xs[5], xe[5], ys[5], ye[5];
    float invx[5], invy[5];
#pragma unroll
    for (int k = 0; k < 5; k++) {
        xs[k] = x1 + (k * Lx) / 5;
        xe[k] = x1 + ((k + 1) * Lx + 4) / 5;
        ys[k] = y1 + (k * Ly) / 5;
        ye[k] = y1 + ((k + 1) * Ly + 4) / 5;
        invx[k] = 1.f / (float)(xe[k] - xs[k]);
        invy[k] = 1.f / (float)(ye[k] - ys[k]);
    }

    const int warp = threadIdx.x >> 5, lane = threadIdx.x & 31;
    const int c = blockIdx.y * 8 + warp;
    const int cb = x1 & ~1;
    const int col0 = cb + 2 * lane, col1 = col0 + 1;
    const bool inx = (col1 >= x1) && (col0 < x2);
    const __half2* ch2 = (const __half2*)(g_attrh + ((long)b * OC + c) * HW) +
                         (cb >> 1) + lane;

    float2 cs[5];
#pragma unroll
    for (int p = 0; p < 5; p++) cs[p] = make_float2(0.f, 0.f);

    if (inx) {
#pragma unroll
        for (int p = 0; p < 5; p++) {
            float sx = 0.f, sy = 0.f;
            for (int h = ys[p]; h < ye[p]; ++h) {
                const float2 v = __half22float2(ch2[h * 32]);
                sx += v.x;
                sy += v.y;
            }
            cs[p].x = sx * invy[p];
            cs[p].y = sy * invy[p];
        }
    }

    float bins[25];
#pragma unroll
    for (int q = 0; q < 5; q++) {
        const float w0 = (col0 >= xs[q] && col0 < xe[q]) ? invx[q] : 0.f;
        const float w1 = (col1 >= xs[q] && col1 < xe[q]) ? invx[q] : 0.f;
#pragma unroll
        for (int p = 0; p < 5; p++)
            bins[p * 5 + q] = cs[p].x * w0 + cs[p].y * w1;
    }
#pragma unroll
    for (int t = 0; t < 25; t++) {
        float v = bins[t];
        v += __shfl_xor_sync(0xffffffffu, v, 16);
        v += __shfl_xor_sync(0xffffffffu, v, 8);
        v += __shfl_xor_sync(0xffffffffu, v, 4);
        v += __shfl_xor_sync(0xffffffffu, v, 2);
        v += __shfl_xor_sync(0xffffffffu, v, 1);
        bins[t] = v;
    }
    if (lane < 25) {
        float vout = 0.f;
#pragma unroll
        for (int t = 0; t < 25; t++)
            if (lane == t) vout = bins[t];
        obj[((long)br * OC + c) * 25 + lane] = vout;
    }
}

__global__ void copy_boxes_kernel(const float* __restrict__ boxes,
                                  float* __restrict__ out) {
    int i = blockIdx.x * blockDim.x + threadIdx.x;
    if (i < 640) out[i] = boxes[i];
}

// ---------------------------------------------------------------------------
extern "C" void kernel_launch(void* const* d_in, const int* in_sizes, int n_in,
                              void* d_out, int out_size) {
    const float* c3    = (const float*)d_in[0];
    const float* c4    = (const float*)d_in[1];
    const float* boxes = (const float*)d_in[2];
    const float* w     = (const float*)d_in[3];
    const float* bconv = (const float*)d_in[4];
    const float* gamma = (const float*)d_in[5];
    const float* beta  = (const float*)d_in[6];
    const float* mean  = (const float*)d_in[7];
    const float* var   = (const float*)d_in[8];

    float* out = (float*)d_out;
    float* obj = out;
    if (out_size >= 640 + 16 * 10 * 512 * 25) {
        copy_boxes_kernel<<<3, 256>>>(boxes, out);
        obj = out + 640;
    }

    cudaFuncSetAttribute(gemm_kernel, cudaFuncAttributeMaxDynamicSharedMemorySize,
                         GEMM_SMEM);

    wpack_kernel<<<(32 * NKT * 32 + 255) / 256, 256>>>(w);
    fuse_kernel<<<dim3(16, 24, 16), 256>>>(c3, c4);
    gemm_kernel<<<dim3(4, 512), 256, GEMM_SMEM>>>(bconv, gamma, beta, mean, var);
    pool_kernel<<<dim3(160, 64), 256>>>(boxes, obj);
}

// round 16
// speedup vs baseline: 1.5482x; 1.0325x over previous
#include <cuda_runtime.h>
#include <cuda_fp16.h>
#include <cstdint>

// ---------------------------------------------------------------------------
//   c3   : [16, 512, 64, 64] f32
//   c4   : [16,1024, 32, 32] f32
//   boxes: [16, 10, 4] f32
//   w    : [512, 1536] f32
//   out  : boxes (640 f32) ++ obj_blob [16,10,512,5,5]
// ---------------------------------------------------------------------------
#define OC   512
#define HW   4096
#define KD   1536
#define NKT  96                    // K / 16

// Scratch (device globals — allocation-free)
__device__ __align__(128) uint32_t g_wpack[OC * KD / 2];          // 1.5 MB
__device__ __align__(128) uint32_t g_bpack[16L * HW * KD / 2];    // 192 MB
__device__ __align__(128) __half   g_attrh[16L * OC * HW + 256];  // 64 MB fp16

// ---------------------------------------------------------------------------
// PTX helpers (baseline ISA only)
// ---------------------------------------------------------------------------
__device__ __forceinline__ uint32_t smem_u32(const void* p) {
    uint32_t a;
    asm("{ .reg .u64 t; cvta.to.shared.u64 t, %1; cvt.u32.u64 %0, t; }" : "=r"(a) : "l"(p));
    return a;
}
__device__ __forceinline__ void cp16(uint32_t dst, const void* src) {
    asm volatile("cp.async.cg.shared.global [%0], [%1], 16;" :: "r"(dst), "l"(src));
}
#define CP_COMMIT() asm volatile("cp.async.commit_group;" ::: "memory")
#define CP_WAIT1()  asm volatile("cp.async.wait_group 1;" ::: "memory")

__device__ __forceinline__ uint32_t pack_h2(float lo, float hi) {
    __half2 h = __floats2half2_rn(lo, hi);
    return *(uint32_t*)&h;
}
__device__ __forceinline__ void mma_f16(float* c, const uint32_t* a,
                                        uint32_t b0, uint32_t b1) {
    asm volatile(
        "mma.sync.aligned.m16n8k16.row.col.f32.f16.f16.f32 "
        "{%0,%1,%2,%3}, {%4,%5,%6,%7}, {%8,%9}, {%0,%1,%2,%3};"
        : "+f"(c[0]), "+f"(c[1]), "+f"(c[2]), "+f"(c[3])
        : "r"(a[0]), "r"(a[1]), "r"(a[2]), "r"(a[3]), "r"(b0), "r"(b1));
}

// ---------------------------------------------------------------------------
// Kernel 0: pack W -> fp16 A-fragment order (m16n8k16 layout)
// ---------------------------------------------------------------------------
__global__ void wpack_kernel(const float* __restrict__ w) {
    const int i = blockIdx.x * 256 + threadIdx.x;
    if (i >= 32 * NKT * 32) return;
    const int t = i >> 5, lane = i & 31;
    const int mt = t / NKT, kt = t % NKT;
    const int r = lane >> 2, c = lane & 3;
    const float* w0 = w + (long)(mt * 16 + r) * KD + kt * 16 + 2 * c;
    const float* w8 = w0 + 8 * KD;
    uint4 v;
    v.x = pack_h2(w0[0], w0[1]);
    v.y = pack_h2(w8[0], w8[1]);
    v.z = pack_h2(w0[8], w0[9]);
    v.w = pack_h2(w8[8], w8[9]);
    ((uint4*)g_wpack)[i] = v;
}

// ---------------------------------------------------------------------------
// Kernel 1: fused = concat(c3, bilinear2x(c4)) -> fp16 B-fragment-packed
//   grid (16 b, 24 ctile, 16 hquad), block 256.  Block: 64 ch x 64 w x 4 h.
// ---------------------------------------------------------------------------
__global__ __launch_bounds__(256) void fuse_kernel(const float* __restrict__ c3,
                                                   const float* __restrict__ c4) {
    __shared__ uint32_t s[4][64][33];       // [h][w][c2]: channels 2c2, 2c2+1
    const int b   = blockIdx.x;
    const int ct  = blockIdx.y;
    const int h0  = blockIdx.z * 4;
    const int tid = threadIdx.x;
    const int c0  = ct * 64;

    if (c0 < 512) {
#pragma unroll
        for (int hh = 0; hh < 4; ++hh) {
#pragma unroll
            for (int it = 0; it < 2; ++it) {
                const int i  = tid + it * 256;
                const int w4 = i & 15, c2 = i >> 4;
                const long base = (((long)(b * 512 + c0 + 2 * c2)) << 12) +
                                  (h0 + hh) * 64 + w4 * 4;
                const float4 f0 = *(const float4*)(c3 + base);
                const float4 f1 = *(const float4*)(c3 + base + HW);
                s[hh][w4 * 4 + 0][c2] = pack_h2(f0.x, f1.x);
                s[hh][w4 * 4 + 1][c2] = pack_h2(f0.y, f1.y);
                s[hh][w4 * 4 + 2][c2] = pack_h2(f0.z, f1.z);
                s[hh][w4 * 4 + 3][c2] = pack_h2(f0.w, f1.w);
            }
        }
    } else {
        const int cc0 = c0 - 512;
#pragma unroll
        for (int hh = 0; hh < 4; ++hh) {
            const int h = h0 + hh;
            const float syf = h * 0.5f - 0.25f;
            const float y0f = floorf(syf);
            const float fy  = syf - y0f;
            const int  iy0 = max(0, min(31, (int)y0f));
            const int  iy1 = max(0, min(31, (int)y0f + 1));
#pragma unroll
            for (int it = 0; it < 2; ++it) {
                const int i  = tid + it * 256;
                const int w4 = i & 15, c2 = i >> 4;
                const float* srcA = c4 + ((long)(b * 1024 + cc0 + 2 * c2)) * 1024;
                const float* srcB = srcA + 1024;
                const float* a0 = srcA + iy0 * 32;
                const float* a1 = srcA + iy1 * 32;
                const float* b0p = srcB + iy0 * 32;
                const float* b1p = srcB + iy1 * 32;
#pragma unroll
                for (int j = 0; j < 4; ++j) {
                    const int w = w4 * 4 + j;
                    const float sxf = w * 0.5f - 0.25f;
                    const float x0f = floorf(sxf);
                    const float fx  = sxf - x0f;
                    const int ix0 = max(0, min(31, (int)x0f));
                    const int ix1 = max(0, min(31, (int)x0f + 1));
                    const float wa = (1.f - fx) * (1.f - fy), wb = fx * (1.f - fy);
                    const float wc = (1.f - fx) * fy,          wd = fx * fy;
                    const float vA = a0[ix0] * wa + a0[ix1] * wb +
                                     a1[ix0] * wc + a1[ix1] * wd;
                    const float vB = b0p[ix0] * wa + b0p[ix1] * wb +
                                     b1p[ix0] * wc + b1p[ix1] * wd;
                    s[hh][w][c2] = pack_h2(vA, vB);
                }
            }
        }
    }
    __syncthreads();

    for (int i = tid; i < 1024; i += 256) {
        const int w   = i & 63;
        const int ktl = (i >> 6) & 3;
        const int hh  = i >> 8;
        const uint32_t* row = &s[hh][w][0] + ktl * 8;
        uint4 lo = make_uint4(row[0], row[4], row[1], row[5]);
        uint4 hi = make_uint4(row[2], row[6], row[3], row[7]);
        const int  h    = h0 + hh;
        const long nt   = (long)b * 512 + ((h * 64 + w) >> 3);
        const long base = (nt * NKT + ct * 4 + ktl) * 64 + (w & 7) * 8;
        *(uint4*)(g_bpack + base)     = lo;
        *(uint4*)(g_bpack + base + 4) = hi;
    }
}

// ---------------------------------------------------------------------------
// Kernel 2: fp16 mma.sync GEMM, BK=64, 3-stage single-sync cp.async pipeline
//   CTA 128x128, 8 warps (2m x 4n), warp tile 64x32.  grid (4, 512).
//   24 mainloop iters (was 48): half the barriers, 64-MMA bursts.
// ---------------------------------------------------------------------------
#define STAGES    3
#define A_BYTES   16384
#define B_OFF     A_BYTES
#define STG_BYTES 32768            // A 16KB + B 16KB per stage
#define BN_OFF    (STAGES * STG_BYTES)      // 98304
#define GEMM_SMEM (BN_OFF + 1024)

__global__ __launch_bounds__(256, 2)
void gemm_kernel(const float* __restrict__ bconv, const float* __restrict__ gamma,
                 const float* __restrict__ beta,  const float* __restrict__ mean,
                 const float* __restrict__ var) {
    extern __shared__ char smem[];
    const uint32_t sb = smem_u32(smem);
    const int tid  = threadIdx.x;
    const int wid  = tid >> 5, lane = tid & 31;
    const int wm   = wid >> 2;
    const int wn   = wid & 3;
    const int m0   = blockIdx.x * 128;
    const int ny   = blockIdx.y;
    const int bI   = ny >> 5;
    const int hw0  = (ny & 31) * 128;

    float* s_inv  = (float*)(smem + BN_OFF);
    float* s_bias = s_inv + 128;
    if (tid < 128) {
        const int o = m0 + tid;
        const float iv = gamma[o] * rsqrtf(var[o] + 1e-5f);
        s_inv[tid]  = iv;
        s_bias[tid] = (bconv[o] - mean[o]) * iv + beta[o];
    }

    const uint4* Wp = (const uint4*)g_wpack;
    const uint4* Bp = (const uint4*)g_bpack;
    const int  mtb = blockIdx.x * 8;
    const long ntb = (long)bI * 512 + (ny & 31) * 16;

    // per-thread load slots: 4 uint4 for A, 4 for B per stage (BK=64)
    long  aG[4], bG[4];
    uint32_t aS[4], bS[4];
#pragma unroll
    for (int j = 0; j < 4; ++j) {
        const int u = tid + j * 256;           // 0..1023
        {   // A: u -> (mt_l = u>>7, kt_l = (u>>5)&3, ln = u&31)
            const int mt_l = u >> 7, kt_l = (u >> 5) & 3, ln = u & 31;
            aG[j] = ((long)(mtb + mt_l) * NKT + kt_l) * 32 + ln;
            aS[j] = (uint32_t)u * 16;
        }
        {   // B: u -> (nt_l = u>>6, kt_l = (u>>4)&3, p = u&15)
            const int nt_l = u >> 6, kt_l = (u >> 4) & 3, p = u & 15;
            bG[j] = ((ntb + nt_l) * NKT + kt_l) * 16 + p;
            bS[j] = (uint32_t)(B_OFF + u * 16);
        }
    }

    auto load_stage = [&](int buf, int t) {
        const uint32_t stg = sb + buf * STG_BYTES;
#pragma unroll
        for (int j = 0; j < 4; ++j) {
            cp16(stg + aS[j], Wp + aG[j] + (long)t * 128);   // 4 kt x 32 uint4
            cp16(stg + bS[j], Bp + bG[j] + (long)t * 64);    // 4 kt x 16 uint4
        }
    };

    float acc[4][4][4];
#pragma unroll
    for (int i = 0; i < 4; i++)
#pragma unroll
        for (int j = 0; j < 4; j++)
#pragma unroll
            for (int k = 0; k < 4; k++) acc[i][j][k] = 0.f;

    // prologue: 2 stages in flight
    load_stage(0, 0); CP_COMMIT();
    load_stage(1, 1); CP_COMMIT();

    int buf = 0;
    for (int t = 0; t < 24; ++t) {
        CP_WAIT1();                 // stage t complete (<=1 newer pending)
        __syncthreads();            // all warps see stage t + compute(t-1) done
        if (t + 2 < 24) {
            int nb = buf + 2; if (nb >= 3) nb -= 3;
            load_stage(nb, t + 2);
        }
        CP_COMMIT();                // uniform commit keeps group accounting

        const uint32_t stg = sb + buf * STG_BYTES;
#pragma unroll
        for (int kg = 0; kg < 4; ++kg) {
            uint32_t bf[4][2];
#pragma unroll
            for (int nf = 0; nf < 4; ++nf) {
                const uint32_t ba = stg + B_OFF +
                    (uint32_t)(((wn * 4 + nf) * 4 + kg) * 256 + lane * 8);
                asm volatile("ld.shared.v2.b32 {%0,%1}, [%2];"
                             : "=r"(bf[nf][0]), "=r"(bf[nf][1]) : "r"(ba));
            }
#pragma unroll
            for (int mf = 0; mf < 4; ++mf) {
                uint32_t af[4];
                const uint32_t aa = stg +
                    (uint32_t)((((wm * 4 + mf) * 4 + kg) * 32 + lane) * 16);
                asm volatile("ld.shared.v4.b32 {%0,%1,%2,%3}, [%4];"
                             : "=r"(af[0]), "=r"(af[1]), "=r"(af[2]), "=r"(af[3])
                             : "r"(aa));
#pragma unroll
                for (int nf = 0; nf < 4; ++nf)
                    mma_f16(acc[mf][nf], af, bf[nf][0], bf[nf][1]);
            }
        }
        if (++buf >= 3) buf = 0;
    }

    const int g = lane >> 2, tq = lane & 3;
    __half* attrh = g_attrh + ((long)bI * OC + m0) * HW + hw0;
#pragma unroll
    for (int mf = 0; mf < 4; ++mf) {
        const int ml0 = wm * 64 + mf * 16 + g;
        const int ml1 = ml0 + 8;
        const float i0 = s_inv[ml0], z0 = s_bias[ml0];
        const float i1 = s_inv[ml1], z1 = s_bias[ml1];
#pragma unroll
        for (int nf = 0; nf < 4; ++nf) {
            const int n = wn * 32 + nf * 8 + 2 * tq;
            *(__half2*)(attrh + (long)ml0 * HW + n) =
                __floats2half2_rn(fmaxf(acc[mf][nf][0] * i0 + z0, 0.f),
                                  fmaxf(acc[mf][nf][1] * i0 + z0, 0.f));
            *(__half2*)(attrh + (long)ml1 * HW + n) =
                __floats2half2_rn(fmaxf(acc[mf][nf][2] * i1 + z1, 0.f),
                                  fmaxf(acc[mf][nf][3] * i1 + z1, 0.f));
        }
    }
}

// ---------------------------------------------------------------------------
// Kernel 3: ROI adaptive-avg-pool 5x5 over fp16 attr.  grid (160, 64).
//   Bin-outer row loops; lanes outside the box skip all loads.
// ---------------------------------------------------------------------------
__global__ __launch_bounds__(256) void pool_kernel(const float* __restrict__ boxes,
                                                   float* __restrict__ obj) {
    const int br = blockIdx.x;
    const int b  = br / 10;
    const float* bx = boxes + br * 4;

    int x1 = min(63, max(0, (int)floorf(bx[0] * 0.125f)));
    int y1 = min(63, max(0, (int)floorf(bx[1] * 0.125f)));
    int x2 = min(63, max(0, (int)ceilf (bx[2] * 0.125f)));
    int y2 = min(63, max(0, (int)ceilf (bx[3] * 0.125f)));
    if (x2 <= x1) x2 = min(x1 + 1, 64);
    if (y2 <= y1) y2 = min(y1 + 1, 64);
    const int Lx = x2 - x1, Ly = y2 - y1;

    int xs[5], xe[5], ys[5], ye[5];
    float invx[5], invy[5];
#pragma unroll
    for (int k = 0; k < 5; k++) {
        xs[k] = x1 + (k * Lx) / 5;
        xe[k] = x1 + ((k + 1) * Lx + 4) / 5;
        ys[k] = y1 + (k * Ly) / 5;
        ye[k] = y1 + ((k + 1) * Ly + 4) / 5;
        invx[k] = 1.f / (float)(xe[k] - xs[k]);
        invy[k] = 1.f / (float)(ye[k] - ys[k]);
    }

    const int warp = threadIdx.x >> 5, lane = threadIdx.x & 31;
    const int c = blockIdx.y * 8 + warp;
    const int cb = x1 & ~1;
    const int col0 = cb + 2 * lane, col1 = col0 + 1;
    const bool inx = (col1 >= x1) && (col0 < x2);
    const __half2* ch2 = (const __half2*)(g_attrh + ((long)b * OC + c) * HW) +
                         (cb >> 1) + lane;

    float2 cs[5];
#pragma unroll
    for (int p = 0; p < 5; p++) cs[p] = make_float2(0.f, 0.f);

    if (inx) {
#pragma unroll
        for (int p = 0; p < 5; p++) {
            float sx = 0.f, sy = 0.f;
            for (int h = ys[p]; h < ye[p]; ++h) {
                const float2 v = __half22float2(ch2[h * 32]);
                sx += v.x;
                sy += v.y;
            }
            cs[p].x = sx * invy[p];
            cs[p].y = sy * invy[p];
        }
    }

    float bins[25];
#pragma unroll
    for (int q = 0; q < 5; q++) {
        const float w0 = (col0 >= xs[q] && col0 < xe[q]) ? invx[q] : 0.f;
        const float w1 = (col1 >= xs[q] && col1 < xe[q]) ? invx[q] : 0.f;
#pragma unroll
        for (int p = 0; p < 5; p++)
            bins[p * 5 + q] = cs[p].x * w0 + cs[p].y * w1;
    }
#pragma unroll
    for (int t = 0; t < 25; t++) {
        float v = bins[t];
        v += __shfl_xor_sync(0xffffffffu, v, 16);
        v += __shfl_xor_sync(0xffffffffu, v, 8);
        v += __shfl_xor_sync(0xffffffffu, v, 4);
        v += __shfl_xor_sync(0xffffffffu, v, 2);
        v += __shfl_xor_sync(0xffffffffu, v, 1);
        bins[t] = v;
    }
    if (lane < 25) {
        float vout = 0.f;
#pragma unroll
        for (int t = 0; t < 25; t++)
            if (lane == t) vout = bins[t];
        obj[((long)br * OC + c) * 25 + lane] = vout;
    }
}

__global__ void copy_boxes_kernel(const float* __restrict__ boxes,
                                  float* __restrict__ out) {
    int i = blockIdx.x * blockDim.x + threadIdx.x;
    if (i < 640) out[i] = boxes[i];
}

// ---------------------------------------------------------------------------
extern "C" void kernel_launch(void* const* d_in, const int* in_sizes, int n_in,
                              void* d_out, int out_size) {
    const float* c3    = (const float*)d_in[0];
    const float* c4    = (const float*)d_in[1];
    const float* boxes = (const float*)d_in[2];
    const float* w     = (const float*)d_in[3];
    const float* bconv = (const float*)d_in[4];
    const float* gamma = (const float*)d_in[5];
    const float* beta  = (const float*)d_in[6];
    const float* mean  = (const float*)d_in[7];
    const float* var   = (const float*)d_in[8];

    float* out = (float*)d_out;
    float* obj = out;
    if (out_size >= 640 + 16 * 10 * 512 * 25) {
        copy_boxes_kernel<<<3, 256>>>(boxes, out);
        obj = out + 640;
    }

    cudaFuncSetAttribute(gemm_kernel, cudaFuncAttributeMaxDynamicSharedMemorySize,
                         GEMM_SMEM);

    wpack_kernel<<<(32 * NKT * 32 + 255) / 256, 256>>>(w);
    fuse_kernel<<<dim3(16, 24, 16), 256>>>(c3, c4);
    gemm_kernel<<<dim3(4, 512), 256, GEMM_SMEM>>>(bconv, gamma, beta, mean, var);
    pool_kernel<<<dim3(160, 64), 256>>>(boxes, obj);
}